// round 7
// baseline (speedup 1.0000x reference)
#include <cuda_runtime.h>
#include <cstdint>

#define NB 16
#define NO 64
#define LOCS 1024
#define KVOL 576                 // 64 ch * 3 * 3
#define NKB 36                   // 16-k blocks

// B-fragment smem: 288 kpairs x 16 slots x 16B (hi0,hi1,lo0,lo1 per slot)
#define SMEM_B_BYTES (288 * 16 * 16)

__device__ float g_xT[64 * 32 * 32 * NB];          // (c,h,w,b), 4 MB
__device__ float g_ps[64 * NO], g_ps2[64 * NO];    // bucketed BN partials
__device__ float g_scale[NO], g_shift[NO];

__device__ __forceinline__ uint32_t tf32_rna(float f) {
    uint32_t u;
    asm("cvt.rna.tf32.f32 %0, %1;" : "=r"(u) : "f"(f));
    return u;
}
__device__ __forceinline__ void mma_tf32(float* d, const uint32_t* a, uint32_t b0,
                                         uint32_t b1) {
    asm volatile(
        "mma.sync.aligned.m16n8k8.row.col.f32.tf32.tf32.f32 "
        "{%0,%1,%2,%3}, {%4,%5,%6,%7}, {%8,%9}, {%0,%1,%2,%3};"
        : "+f"(d[0]), "+f"(d[1]), "+f"(d[2]), "+f"(d[3])
        : "r"(a[0]), "r"(a[1]), "r"(a[2]), "r"(a[3]), "r"(b0), "r"(b1));
}

// ---------------------------------------------------------------------------
// x (b,c,h,w) -> xT (c,h,w,b); first 16 blocks also zero the BN partials.
// ---------------------------------------------------------------------------
__global__ __launch_bounds__(256) void transpose_kernel(const float* __restrict__ x) {
    int idx = blockIdx.x * 256 + threadIdx.x;
    if (blockIdx.x < 16) { g_ps[idx] = 0.f; g_ps2[idx] = 0.f; }
    int b = idx & 15, w = (idx >> 4) & 31, h = (idx >> 9) & 31, c = idx >> 14;
    g_xT[idx] = x[(((b << 6) + c) << 10) + (h << 5) + w];
}

// ---------------------------------------------------------------------------
// One CTA (128 thr, 4 warps) per output location.
// D[64 x 16] = W_loc[64 x 576] * X_loc[576 x 16] via mma.sync tf32, with X
// split exactly into hi+lo tf32 terms (W single tf32-RNA).
//
// k-permutation: within a 16-k block kb, mma step s (0/1), lane tg = lane&3:
//   A logical cols (tg, tg+4) = actual k (K0+4tg+2s, K0+4tg+2s+1)  -> one
//   float4 per row covers both steps. B fragment rows are the same k pair.
// B smem slot for (kpair kp, col n): 16B = (bh_even, bh_odd, bl_even, bl_odd)
// at byte 16*(kp*16 + ((n + kp) & 15))   [conflict-free per 8-lane phase].
// ---------------------------------------------------------------------------
__global__ __launch_bounds__(128) void conv_mma_kernel(const float* __restrict__ wgt,
                                                       const float* __restrict__ bias,
                                                       float* __restrict__ out) {
    extern __shared__ uint32_t bsm[];                // SMEM_B_BYTES
    const int tid = threadIdx.x, wid = tid >> 5, lane = tid & 31;
    const int tg = lane & 3, g = lane >> 2;
    const int loc = blockIdx.x, li = loc >> 5, lj = loc & 31;

    // ---- Stage B = X hi/lo fragments ----
    for (int t = tid; t < 288 * 4; t += 128) {
        int kp = t >> 2, nq = t & 3;                 // kpair, n-quad
        float4 xq[2];
#pragma unroll
        for (int h = 0; h < 2; h++) {
            int k = 2 * kp + h;
            int c = k / 9, r = k - c * 9, p = r / 3, q = r - p * 3;
            int ih = li + p - 1, iw = lj + q - 1;
            xq[h] = make_float4(0.f, 0.f, 0.f, 0.f);
            if ((unsigned)ih < 32u && (unsigned)iw < 32u)
                xq[h] = *(const float4*)&g_xT[(((((c << 5) + ih) << 5) + iw) << 4) + (nq << 2)];
        }
        const float* x0 = &xq[0].x;
        const float* x1 = &xq[1].x;
#pragma unroll
        for (int e = 0; e < 4; e++) {
            int n = (nq << 2) + e;
            uint32_t h0 = tf32_rna(x0[e]);
            uint32_t h1 = tf32_rna(x1[e]);
            uint32_t l0 = tf32_rna(x0[e] - __uint_as_float(h0));
            uint32_t l1 = tf32_rna(x1[e] - __uint_as_float(h1));
            uint32_t slot = (uint32_t)kp * 16u + (uint32_t)((n + kp) & 15);
            *(uint4*)&bsm[slot << 2] = make_uint4(h0, h1, l0, l1);
        }
    }
    __syncthreads();

    // ---- Main loop: warp wid owns output rows o = 16*wid .. 16*wid+15 ----
    const float* wrow0 = wgt + ((size_t)((wid << 4) + g) * LOCS + loc) * KVOL + (tg << 2);
    const float* wrow8 = wrow0 + (size_t)8 * LOCS * KVOL;

    float d[2][4] = {{0.f, 0.f, 0.f, 0.f}, {0.f, 0.f, 0.f, 0.f}};

    float4 A0 = *(const float4*)wrow0;
    float4 A1 = *(const float4*)wrow8;

#pragma unroll 4
    for (int kb = 0; kb < NKB; kb++) {
        float4 A0n, A1n;
        if (kb < NKB - 1) {
            A0n = *(const float4*)(wrow0 + (kb + 1) * 16);
            A1n = *(const float4*)(wrow8 + (kb + 1) * 16);
        }
#pragma unroll
        for (int s = 0; s < 2; s++) {
            uint32_t a[4];
            a[0] = tf32_rna(s ? A0.z : A0.x);
            a[1] = tf32_rna(s ? A1.z : A1.x);
            a[2] = tf32_rna(s ? A0.w : A0.y);
            a[3] = tf32_rna(s ? A1.w : A1.y);
            int kp = (kb << 3) + (tg << 1) + s;
#pragma unroll
            for (int nt = 0; nt < 2; nt++) {
                int n = g + (nt << 3);
                uint32_t slot = (uint32_t)kp * 16u + (uint32_t)((n + kp) & 15);
                uint4 q = *(const uint4*)&bsm[slot << 2];
                mma_tf32(d[nt], a, q.x, q.y);        // hi term
                mma_tf32(d[nt], a, q.z, q.w);        // lo term
            }
        }
        A0 = A0n;
        A1 = A1n;
    }

    // ---- Epilogue: lane (g,tg) holds rows o0=16w+g, o1=o0+8;
    //      cols b = {2tg, 2tg+1} per n-tile (nt<<3 offset). ----
    int o0 = (wid << 4) + g, o1 = o0 + 8;
    float bv0 = bias[(o0 << 10) + loc];
    float bv1 = bias[(o1 << 10) + loc];
    float s0 = 0.f, q0 = 0.f, s1 = 0.f, q1 = 0.f;
#pragma unroll
    for (int nt = 0; nt < 2; nt++) {
#pragma unroll
        for (int e = 0; e < 2; e++) {
            int b = (nt << 3) + (tg << 1) + e;
            float v0 = d[nt][e] + bv0;               // c0/c1 -> row o0
            float v1 = d[nt][e + 2] + bv1;           // c2/c3 -> row o1
            out[(((b << 6) + o0) << 10) + loc] = v0;
            out[(((b << 6) + o1) << 10) + loc] = v1;
            s0 += v0; q0 = fmaf(v0, v0, q0);
            s1 += v1; q1 = fmaf(v1, v1, q1);
        }
    }
    // Reduce over the 4 tg-lanes of this g-group (covers all 16 batches).
#pragma unroll
    for (int m = 1; m < 4; m <<= 1) {
        s0 += __shfl_down_sync(0xffffffffu, s0, m, 4);
        q0 += __shfl_down_sync(0xffffffffu, q0, m, 4);
        s1 += __shfl_down_sync(0xffffffffu, s1, m, 4);
        q1 += __shfl_down_sync(0xffffffffu, q1, m, 4);
    }
    if (tg == 0) {
        int bkt = loc & 63;
        atomicAdd(&g_ps[(bkt << 6) + o0], s0);
        atomicAdd(&g_ps2[(bkt << 6) + o0], q0);
        atomicAdd(&g_ps[(bkt << 6) + o1], s1);
        atomicAdd(&g_ps2[(bkt << 6) + o1], q1);
    }
}

// ---------------------------------------------------------------------------
__global__ void params_kernel(const float* __restrict__ gamma,
                              const float* __restrict__ beta) {
    int o = threadIdx.x;
    float S = 0.f, S2 = 0.f;
    for (int k = 0; k < 64; k++) { S += g_ps[(k << 6) + o]; S2 += g_ps2[(k << 6) + o]; }
    const float inv = 1.f / (float)(NB * LOCS);
    float mean = S * inv;
    float var = S2 * inv - mean * mean;              // biased variance (ddof=0)
    float sc = gamma[o] * rsqrtf(var + 1e-5f);
    g_scale[o] = sc;
    g_shift[o] = beta[o] - mean * sc;
}

__global__ __launch_bounds__(256) void finalize_kernel(float* __restrict__ y) {
    int idx = blockIdx.x * 256 + threadIdx.x;
    int o = (idx >> 8) & 63;
    float sc = g_scale[o], sh = g_shift[o];
    float4 v = ((float4*)y)[idx];
    v.x = fmaxf(fmaf(v.x, sc, sh), 0.f);
    v.y = fmaxf(fmaf(v.y, sc, sh), 0.f);
    v.z = fmaxf(fmaf(v.z, sc, sh), 0.f);
    v.w = fmaxf(fmaf(v.w, sc, sh), 0.f);
    ((float4*)y)[idx] = v;
}

extern "C" void kernel_launch(void* const* d_in, const int* in_sizes, int n_in,
                              void* d_out, int out_size) {
    const float* x     = (const float*)d_in[0];
    const float* w     = (const float*)d_in[1];
    const float* bias  = (const float*)d_in[2];
    const float* gamma = (const float*)d_in[3];
    const float* beta  = (const float*)d_in[4];
    float* out = (float*)d_out;

    cudaFuncSetAttribute(conv_mma_kernel, cudaFuncAttributeMaxDynamicSharedMemorySize,
                         SMEM_B_BYTES);

    transpose_kernel<<<4096, 256>>>(x);                  // + zero BN partials
    conv_mma_kernel<<<1024, 128, SMEM_B_BYTES>>>(w, bias, out);
    params_kernel<<<1, 64>>>(gamma, beta);
    finalize_kernel<<<1024, 256>>>(out);
}

// round 9
// speedup vs baseline: 1.1558x; 1.1558x over previous
#include <cuda_runtime.h>
#include <cstdint>

#define NB 16
#define NO 64
#define LOCS 1024
#define KVOL 576                 // 64 ch * 3 * 3
#define NKB 36                   // 16-k blocks
#define NST 6                    // W cp.async pipeline depth

#define SMEM_B_BYTES (288 * 16 * 16)        // 73728: B hi/lo fragment slots
#define SMEM_W_BYTES (NST * 4 * 1024)       // 24576: NST stages x 4 warps x 1KB
#define SMEM_TOTAL   (SMEM_B_BYTES + SMEM_W_BYTES)

__device__ float g_xT[64 * 32 * 32 * NB];          // (c,h,w,b), 4 MB
__device__ float g_ps[64 * NO], g_ps2[64 * NO];    // bucketed BN partials
__device__ float g_scale[NO], g_shift[NO];

__device__ __forceinline__ uint32_t tf32_rna(float f) {
    uint32_t u;
    asm("cvt.rna.tf32.f32 %0, %1;" : "=r"(u) : "f"(f));
    return u;
}
__device__ __forceinline__ void mma_tf32(float* d, const uint32_t* a, uint32_t b0,
                                         uint32_t b1) {
    asm volatile(
        "mma.sync.aligned.m16n8k8.row.col.f32.tf32.tf32.f32 "
        "{%0,%1,%2,%3}, {%4,%5,%6,%7}, {%8,%9}, {%0,%1,%2,%3};"
        : "+f"(d[0]), "+f"(d[1]), "+f"(d[2]), "+f"(d[3])
        : "r"(a[0]), "r"(a[1]), "r"(a[2]), "r"(a[3]), "r"(b0), "r"(b1));
}
__device__ __forceinline__ void cp16(void* dst_smem, const void* src) {
    unsigned d = (unsigned)__cvta_generic_to_shared(dst_smem);
    asm volatile("cp.async.ca.shared.global [%0], [%1], 16;" :: "r"(d), "l"(src));
}
#define CP_COMMIT() asm volatile("cp.async.commit_group;")
#define CP_WAITG()  asm volatile("cp.async.wait_group %0;" :: "n"(NST - 1))

// ---------------------------------------------------------------------------
// x (b,c,h,w) -> xT (c,h,w,b); first 16 blocks also zero the BN partials.
// ---------------------------------------------------------------------------
__global__ __launch_bounds__(256) void transpose_kernel(const float* __restrict__ x) {
    int idx = blockIdx.x * 256 + threadIdx.x;
    if (blockIdx.x < 16) { g_ps[idx] = 0.f; g_ps2[idx] = 0.f; }
    int b = idx & 15, w = (idx >> 4) & 31, h = (idx >> 9) & 31, c = idx >> 14;
    g_xT[idx] = x[(((b << 6) + c) << 10) + (h << 5) + w];
}

// ---------------------------------------------------------------------------
// One CTA (128 thr, 4 warps) per output location.
// D[64 x 16] = W_loc[64 x 576] * X_loc[576 x 16], mma.sync tf32, X split hi+lo.
// W streams through a warp-private NST-stage cp.async smem pipeline:
//   stage st, warp w -> 1KB block = 16 local rows (o = 16w + r) x 16 k-floats.
//   Fill: lane -> row = lane>>1, half = lane&1 (2 x cp16 = 32B). Consume:
//   lane (g,tg) -> float4 at rows g, g+8, byte tg*16 (linear, conflict-free).
// B smem slot (kpair kp, col n): 16B (bh0,bh1,bl0,bl1) at 16*(kp*16+((n+kp)&15)).
// ---------------------------------------------------------------------------
__global__ __launch_bounds__(128) void conv_mma_kernel(const float* __restrict__ wgt,
                                                       const float* __restrict__ bias,
                                                       float* __restrict__ out) {
    extern __shared__ uint32_t bsm[];                // B fragments
    char* wsm = (char*)bsm + SMEM_B_BYTES;           // W pipeline
    const int tid = threadIdx.x, wid = tid >> 5, lane = tid & 31;
    const int tg = lane & 3, g = lane >> 2;
    const int loc = blockIdx.x, li = loc >> 5, lj = loc & 31;

    // ---- W pipeline prologue (issue first, overlap with B staging) ----
    const int wrow = lane >> 1, whalf = lane & 1;
    const float* wsrc = wgt + ((size_t)((wid << 4) + wrow) * LOCS + loc) * KVOL
                      + (whalf << 3);
    char* wdst0 = wsm + (wid << 10) + wrow * 64 + (whalf << 5);
#pragma unroll
    for (int st = 0; st < NST; st++) {
        cp16(wdst0 + (st << 12), wsrc + st * 16);
        cp16(wdst0 + (st << 12) + 16, wsrc + st * 16 + 4);
        CP_COMMIT();
    }

    // ---- Stage B = X hi/lo fragments ----
    for (int t = tid; t < 288 * 4; t += 128) {
        int kp = t >> 2, nq = t & 3;                 // kpair, n-quad
        float4 xq[2];
#pragma unroll
        for (int h = 0; h < 2; h++) {
            int k = 2 * kp + h;
            int c = k / 9, r = k - c * 9, p = r / 3, q = r - p * 3;
            int ih = li + p - 1, iw = lj + q - 1;
            xq[h] = make_float4(0.f, 0.f, 0.f, 0.f);
            if ((unsigned)ih < 32u && (unsigned)iw < 32u)
                xq[h] = *(const float4*)&g_xT[(((((c << 5) + ih) << 5) + iw) << 4) + (nq << 2)];
        }
        const float* x0 = &xq[0].x;
        const float* x1 = &xq[1].x;
#pragma unroll
        for (int e = 0; e < 4; e++) {
            int n = (nq << 2) + e;
            uint32_t h0 = tf32_rna(x0[e]);
            uint32_t h1 = tf32_rna(x1[e]);
            uint32_t l0 = tf32_rna(x0[e] - __uint_as_float(h0));
            uint32_t l1 = tf32_rna(x1[e] - __uint_as_float(h1));
            uint32_t slot = (uint32_t)kp * 16u + (uint32_t)((n + kp) & 15);
            *(uint4*)&bsm[slot << 2] = make_uint4(h0, h1, l0, l1);
        }
    }
    __syncthreads();

    // ---- Main loop ----
    float d[2][4] = {{0.f, 0.f, 0.f, 0.f}, {0.f, 0.f, 0.f, 0.f}};
    const char* wcons = wsm + (wid << 10) + tg * 16;

    for (int kb = 0; kb < NKB; kb++) {
        CP_WAITG();
        __syncwarp();
        const char* a = wcons + ((kb % NST) << 12);
        float4 A0 = *(const float4*)(a + g * 64);
        float4 A1 = *(const float4*)(a + (g + 8) * 64);
        __syncwarp();                                 // all lanes read before refill
        if (kb + NST < NKB) {
            cp16(wdst0 + ((kb % NST) << 12), wsrc + (kb + NST) * 16);
            cp16(wdst0 + ((kb % NST) << 12) + 16, wsrc + (kb + NST) * 16 + 4);
        }
        CP_COMMIT();                                  // empty group in tail is fine

#pragma unroll
        for (int s = 0; s < 2; s++) {
            uint32_t aa[4];
            aa[0] = tf32_rna(s ? A0.z : A0.x);
            aa[1] = tf32_rna(s ? A1.z : A1.x);
            aa[2] = tf32_rna(s ? A0.w : A0.y);
            aa[3] = tf32_rna(s ? A1.w : A1.y);
            int kp = (kb << 3) + (tg << 1) + s;
#pragma unroll
            for (int nt = 0; nt < 2; nt++) {
                int n = g + (nt << 3);
                uint32_t slot = (uint32_t)kp * 16u + (uint32_t)((n + kp) & 15);
                uint4 q = *(const uint4*)&bsm[slot << 2];
                mma_tf32(d[nt], aa, q.x, q.y);        // hi term
                mma_tf32(d[nt], aa, q.z, q.w);        // lo term
            }
        }
    }

    // ---- Epilogue: lane (g,tg) holds rows o0=16w+g, o1=o0+8;
    //      cols b = {2tg, 2tg+1} per n-tile. ----
    int o0 = (wid << 4) + g, o1 = o0 + 8;
    float bv0 = bias[(o0 << 10) + loc];
    float bv1 = bias[(o1 << 10) + loc];
    float s0 = 0.f, q0 = 0.f, s1 = 0.f, q1 = 0.f;
#pragma unroll
    for (int nt = 0; nt < 2; nt++) {
#pragma unroll
        for (int e = 0; e < 2; e++) {
            int b = (nt << 3) + (tg << 1) + e;
            float v0 = d[nt][e] + bv0;
            float v1 = d[nt][e + 2] + bv1;
            out[(((b << 6) + o0) << 10) + loc] = v0;
            out[(((b << 6) + o1) << 10) + loc] = v1;
            s0 += v0; q0 = fmaf(v0, v0, q0);
            s1 += v1; q1 = fmaf(v1, v1, q1);
        }
    }
#pragma unroll
    for (int m = 1; m < 4; m <<= 1) {
        s0 += __shfl_down_sync(0xffffffffu, s0, m, 4);
        q0 += __shfl_down_sync(0xffffffffu, q0, m, 4);
        s1 += __shfl_down_sync(0xffffffffu, s1, m, 4);
        q1 += __shfl_down_sync(0xffffffffu, q1, m, 4);
    }
    if (tg == 0) {
        int bkt = loc & 63;
        atomicAdd(&g_ps[(bkt << 6) + o0], s0);
        atomicAdd(&g_ps2[(bkt << 6) + o0], q0);
        atomicAdd(&g_ps[(bkt << 6) + o1], s1);
        atomicAdd(&g_ps2[(bkt << 6) + o1], q1);
    }
}

// ---------------------------------------------------------------------------
__global__ void params_kernel(const float* __restrict__ gamma,
                              const float* __restrict__ beta) {
    int o = threadIdx.x;
    float S = 0.f, S2 = 0.f;
    for (int k = 0; k < 64; k++) { S += g_ps[(k << 6) + o]; S2 += g_ps2[(k << 6) + o]; }
    const float inv = 1.f / (float)(NB * LOCS);
    float mean = S * inv;
    float var = S2 * inv - mean * mean;              // biased variance (ddof=0)
    float sc = gamma[o] * rsqrtf(var + 1e-5f);
    g_scale[o] = sc;
    g_shift[o] = beta[o] - mean * sc;
}

__global__ __launch_bounds__(256) void finalize_kernel(float* __restrict__ y) {
    int idx = blockIdx.x * 256 + threadIdx.x;
    int o = (idx >> 8) & 63;
    float sc = g_scale[o], sh = g_shift[o];
    float4 v = ((float4*)y)[idx];
    v.x = fmaxf(fmaf(v.x, sc, sh), 0.f);
    v.y = fmaxf(fmaf(v.y, sc, sh), 0.f);
    v.z = fmaxf(fmaf(v.z, sc, sh), 0.f);
    v.w = fmaxf(fmaf(v.w, sc, sh), 0.f);
    ((float4*)y)[idx] = v;
}

extern "C" void kernel_launch(void* const* d_in, const int* in_sizes, int n_in,
                              void* d_out, int out_size) {
    const float* x     = (const float*)d_in[0];
    const float* w     = (const float*)d_in[1];
    const float* bias  = (const float*)d_in[2];
    const float* gamma = (const float*)d_in[3];
    const float* beta  = (const float*)d_in[4];
    float* out = (float*)d_out;

    cudaFuncSetAttribute(conv_mma_kernel, cudaFuncAttributeMaxDynamicSharedMemorySize,
                         SMEM_TOTAL);

    transpose_kernel<<<4096, 256>>>(x);                  // + zero BN partials
    conv_mma_kernel<<<1024, 128, SMEM_TOTAL>>>(w, bias, out);
    params_kernel<<<1, 64>>>(gamma, beta);
    finalize_kernel<<<1024, 256>>>(out);
}

// round 11
// speedup vs baseline: 1.2526x; 1.0838x over previous
#include <cuda_runtime.h>
#include <cstdint>

#define NB 16
#define NO 64
#define LOCS 1024
#define KVOL 576                 // 64 ch * 3 * 3
#define NKB 36                   // 16-k blocks
#define NST 6                    // W cp.async pipeline depth

#define BSLOT_STRIDE 18                       // slots of 8B per kpair row
#define SMEM_B_BYTES (288 * BSLOT_STRIDE * 8) // 41472: B tf32 fragment slots
#define SMEM_W_BYTES (NST * 4 * 1024)         // 24576: NST stages x 4 warps x 1KB
#define SMEM_TOTAL   (SMEM_B_BYTES + SMEM_W_BYTES)

__device__ float g_xT[64 * 32 * 32 * NB];          // (c,h,w,b), 4 MB
__device__ float g_ps[64 * NO], g_ps2[64 * NO];    // bucketed BN partials
__device__ float g_scale[NO], g_shift[NO];

__device__ __forceinline__ uint32_t tf32_rna(float f) {
    uint32_t u;
    asm("cvt.rna.tf32.f32 %0, %1;" : "=r"(u) : "f"(f));
    return u;
}
__device__ __forceinline__ void mma_tf32(float* d, const uint32_t* a, uint32_t b0,
                                         uint32_t b1) {
    asm volatile(
        "mma.sync.aligned.m16n8k8.row.col.f32.tf32.tf32.f32 "
        "{%0,%1,%2,%3}, {%4,%5,%6,%7}, {%8,%9}, {%0,%1,%2,%3};"
        : "+f"(d[0]), "+f"(d[1]), "+f"(d[2]), "+f"(d[3])
        : "r"(a[0]), "r"(a[1]), "r"(a[2]), "r"(a[3]), "r"(b0), "r"(b1));
}
__device__ __forceinline__ void cp16(void* dst_smem, const void* src) {
    unsigned d = (unsigned)__cvta_generic_to_shared(dst_smem);
    asm volatile("cp.async.ca.shared.global [%0], [%1], 16;" :: "r"(d), "l"(src));
}
#define CP_COMMIT() asm volatile("cp.async.commit_group;")
#define CP_WAITG()  asm volatile("cp.async.wait_group %0;" :: "n"(NST - 1))

// ---------------------------------------------------------------------------
// x (b,c,h,w) -> xT (c,h,w,b); first 16 blocks also zero the BN partials.
// ---------------------------------------------------------------------------
__global__ __launch_bounds__(256) void transpose_kernel(const float* __restrict__ x) {
    int idx = blockIdx.x * 256 + threadIdx.x;
    if (blockIdx.x < 16) { g_ps[idx] = 0.f; g_ps2[idx] = 0.f; }
    int b = idx & 15, w = (idx >> 4) & 31, h = (idx >> 9) & 31, c = idx >> 14;
    g_xT[idx] = x[(((b << 6) + c) << 10) + (h << 5) + w];
}

// ---------------------------------------------------------------------------
// One CTA (128 thr, 4 warps) per output location.
// D[64 x 16] = W_loc[64 x 576] * X_loc[576 x 16], mma.sync tf32 (both operands
// single tf32-RNA; combined rel err ~3e-4 < 1e-3 threshold).
// W streams through a warp-private NST-stage cp.async smem pipeline:
//   stage st, warp w -> 1KB block = 16 local rows (o = 16w + r) x 16 k-floats.
//   Fill: lane -> row = lane>>1, half = lane&1 (2 x cp16 = 32B). Consume:
//   lane (g,tg) -> float4 at rows g, g+8, byte tg*16 (linear, conflict-free).
// B slot (kpair kp, col n): 8B (b_even, b_odd) at byte 8*(kp*18 + n).
//   LDS.64 pair-index (2kp+n) mod 16 = 4*tg+g per 16-lane phase -> bijective,
//   conflict-free.
// ---------------------------------------------------------------------------
__global__ __launch_bounds__(128, 3) void conv_mma_kernel(const float* __restrict__ wgt,
                                                          const float* __restrict__ bias,
                                                          float* __restrict__ out) {
    extern __shared__ uint32_t bsm[];                // B fragments
    char* wsm = (char*)bsm + SMEM_B_BYTES;           // W pipeline
    const int tid = threadIdx.x, wid = tid >> 5, lane = tid & 31;
    const int tg = lane & 3, g = lane >> 2;
    const int loc = blockIdx.x, li = loc >> 5, lj = loc & 31;

    // ---- W pipeline prologue (issue first, overlap with B staging) ----
    const int wrow = lane >> 1, whalf = lane & 1;
    const float* wsrc = wgt + ((size_t)((wid << 4) + wrow) * LOCS + loc) * KVOL
                      + (whalf << 3);
    char* wdst0 = wsm + (wid << 10) + wrow * 64 + (whalf << 5);
#pragma unroll
    for (int st = 0; st < NST; st++) {
        cp16(wdst0 + (st << 12), wsrc + st * 16);
        cp16(wdst0 + (st << 12) + 16, wsrc + st * 16 + 4);
        CP_COMMIT();
    }

    // ---- Stage B = X tf32 fragments ----
    for (int t = tid; t < 288 * 4; t += 128) {
        int kp = t >> 2, nq = t & 3;                 // kpair, n-quad
        float4 xq[2];
#pragma unroll
        for (int h = 0; h < 2; h++) {
            int k = 2 * kp + h;
            int c = k / 9, r = k - c * 9, p = r / 3, q = r - p * 3;
            int ih = li + p - 1, iw = lj + q - 1;
            xq[h] = make_float4(0.f, 0.f, 0.f, 0.f);
            if ((unsigned)ih < 32u && (unsigned)iw < 32u)
                xq[h] = *(const float4*)&g_xT[(((((c << 5) + ih) << 5) + iw) << 4) + (nq << 2)];
        }
        const float* x0 = &xq[0].x;
        const float* x1 = &xq[1].x;
#pragma unroll
        for (int e = 0; e < 4; e++) {
            int n = (nq << 2) + e;
            uint32_t h0 = tf32_rna(x0[e]);
            uint32_t h1 = tf32_rna(x1[e]);
            uint32_t idx = (uint32_t)(kp * BSLOT_STRIDE + n) << 1;
            bsm[idx] = h0;
            bsm[idx + 1] = h1;
        }
    }
    __syncthreads();

    // ---- Main loop ----
    float d[2][4] = {{0.f, 0.f, 0.f, 0.f}, {0.f, 0.f, 0.f, 0.f}};
    const char* wcons = wsm + (wid << 10) + tg * 16;

    for (int kb = 0; kb < NKB; kb++) {
        CP_WAITG();
        __syncwarp();
        const char* a = wcons + ((kb % NST) << 12);
        float4 A0 = *(const float4*)(a + g * 64);
        float4 A1 = *(const float4*)(a + (g + 8) * 64);
        __syncwarp();                                 // all lanes read before refill
        if (kb + NST < NKB) {
            cp16(wdst0 + ((kb % NST) << 12), wsrc + (kb + NST) * 16);
            cp16(wdst0 + ((kb % NST) << 12) + 16, wsrc + (kb + NST) * 16 + 4);
        }
        CP_COMMIT();                                  // empty group in tail is fine

#pragma unroll
        for (int s = 0; s < 2; s++) {
            uint32_t aa[4];
            aa[0] = tf32_rna(s ? A0.z : A0.x);
            aa[1] = tf32_rna(s ? A1.z : A1.x);
            aa[2] = tf32_rna(s ? A0.w : A0.y);
            aa[3] = tf32_rna(s ? A1.w : A1.y);
            int kp = (kb << 3) + (tg << 1) + s;
#pragma unroll
            for (int nt = 0; nt < 2; nt++) {
                int n = g + (nt << 3);
                uint2 q = *(const uint2*)&bsm[(uint32_t)(kp * BSLOT_STRIDE + n) << 1];
                mma_tf32(d[nt], aa, q.x, q.y);
            }
        }
    }

    // ---- Epilogue: lane (g,tg) holds rows o0=16w+g, o1=o0+8;
    //      cols b = {2tg, 2tg+1} per n-tile. ----
    int o0 = (wid << 4) + g, o1 = o0 + 8;
    float bv0 = bias[(o0 << 10) + loc];
    float bv1 = bias[(o1 << 10) + loc];
    float s0 = 0.f, q0 = 0.f, s1 = 0.f, q1 = 0.f;
#pragma unroll
    for (int nt = 0; nt < 2; nt++) {
#pragma unroll
        for (int e = 0; e < 2; e++) {
            int b = (nt << 3) + (tg << 1) + e;
            float v0 = d[nt][e] + bv0;
            float v1 = d[nt][e + 2] + bv1;
            out[(((b << 6) + o0) << 10) + loc] = v0;
            out[(((b << 6) + o1) << 10) + loc] = v1;
            s0 += v0; q0 = fmaf(v0, v0, q0);
            s1 += v1; q1 = fmaf(v1, v1, q1);
        }
    }
#pragma unroll
    for (int m = 1; m < 4; m <<= 1) {
        s0 += __shfl_down_sync(0xffffffffu, s0, m, 4);
        q0 += __shfl_down_sync(0xffffffffu, q0, m, 4);
        s1 += __shfl_down_sync(0xffffffffu, s1, m, 4);
        q1 += __shfl_down_sync(0xffffffffu, q1, m, 4);
    }
    if (tg == 0) {
        int bkt = loc & 63;
        atomicAdd(&g_ps[(bkt << 6) + o0], s0);
        atomicAdd(&g_ps2[(bkt << 6) + o0], q0);
        atomicAdd(&g_ps[(bkt << 6) + o1], s1);
        atomicAdd(&g_ps2[(bkt << 6) + o1], q1);
    }
}

// ---------------------------------------------------------------------------
__global__ void params_kernel(const float* __restrict__ gamma,
                              const float* __restrict__ beta) {
    int o = threadIdx.x;
    float S = 0.f, S2 = 0.f;
    for (int k = 0; k < 64; k++) { S += g_ps[(k << 6) + o]; S2 += g_ps2[(k << 6) + o]; }
    const float inv = 1.f / (float)(NB * LOCS);
    float mean = S * inv;
    float var = S2 * inv - mean * mean;              // biased variance (ddof=0)
    float sc = gamma[o] * rsqrtf(var + 1e-5f);
    g_scale[o] = sc;
    g_shift[o] = beta[o] - mean * sc;
}

__global__ __launch_bounds__(256) void finalize_kernel(float* __restrict__ y) {
    int idx = blockIdx.x * 256 + threadIdx.x;
    int o = (idx >> 8) & 63;
    float sc = g_scale[o], sh = g_shift[o];
    float4 v = ((float4*)y)[idx];
    v.x = fmaxf(fmaf(v.x, sc, sh), 0.f);
    v.y = fmaxf(fmaf(v.y, sc, sh), 0.f);
    v.z = fmaxf(fmaf(v.z, sc, sh), 0.f);
    v.w = fmaxf(fmaf(v.w, sc, sh), 0.f);
    ((float4*)y)[idx] = v;
}

extern "C" void kernel_launch(void* const* d_in, const int* in_sizes, int n_in,
                              void* d_out, int out_size) {
    const float* x     = (const float*)d_in[0];
    const float* w     = (const float*)d_in[1];
    const float* bias  = (const float*)d_in[2];
    const float* gamma = (const float*)d_in[3];
    const float* beta  = (const float*)d_in[4];
    float* out = (float*)d_out;

    cudaFuncSetAttribute(conv_mma_kernel, cudaFuncAttributeMaxDynamicSharedMemorySize,
                         SMEM_TOTAL);

    transpose_kernel<<<4096, 256>>>(x);                  // + zero BN partials
    conv_mma_kernel<<<1024, 128, SMEM_TOTAL>>>(w, bias, out);
    params_kernel<<<1, 64>>>(gamma, beta);
    finalize_kernel<<<1024, 256>>>(out);
}

// round 12
// speedup vs baseline: 1.4092x; 1.1250x over previous
#include <cuda_runtime.h>
#include <cstdint>

#define NB 16
#define NO 64
#define LOCS 1024
#define KVOL 576                 // 64 ch * 3 * 3
#define NKB 36                   // 16-k blocks
#define NSTAGES 9                // stages of 4 kb (256B per row per stage)

#define BSLOT_STRIDE 18                       // slots of 8B per kpair row
#define SMEM_B_BYTES (288 * BSLOT_STRIDE * 8) // 41472: B tf32 fragment slots
#define SMEM_W_BYTES (4 * 2 * 4096)           // 32768: 4 warps x 2 slots x 4KB
#define SMEM_TOTAL   (SMEM_B_BYTES + SMEM_W_BYTES)

__device__ float g_xT[64 * 32 * 32 * NB];          // (c,h,w,b), 4 MB
__device__ float g_ps[64 * NO], g_ps2[64 * NO];    // bucketed BN partials
__device__ float g_scale[NO], g_shift[NO];

__device__ __forceinline__ uint32_t tf32_rna(float f) {
    uint32_t u;
    asm("cvt.rna.tf32.f32 %0, %1;" : "=r"(u) : "f"(f));
    return u;
}
__device__ __forceinline__ void mma_tf32(float* d, const uint32_t* a, uint32_t b0,
                                         uint32_t b1) {
    asm volatile(
        "mma.sync.aligned.m16n8k8.row.col.f32.tf32.tf32.f32 "
        "{%0,%1,%2,%3}, {%4,%5,%6,%7}, {%8,%9}, {%0,%1,%2,%3};"
        : "+f"(d[0]), "+f"(d[1]), "+f"(d[2]), "+f"(d[3])
        : "r"(a[0]), "r"(a[1]), "r"(a[2]), "r"(a[3]), "r"(b0), "r"(b1));
}
__device__ __forceinline__ void cp16(void* dst_smem, const void* src) {
    unsigned d = (unsigned)__cvta_generic_to_shared(dst_smem);
    asm volatile("cp.async.ca.shared.global [%0], [%1], 16;" :: "r"(d), "l"(src));
}
#define CP_COMMIT() asm volatile("cp.async.commit_group;")
#define CP_WAIT1()  asm volatile("cp.async.wait_group 1;")

// ---------------------------------------------------------------------------
// x (b,c,h,w) -> xT (c,h,w,b); first 16 blocks also zero the BN partials.
// ---------------------------------------------------------------------------
__global__ __launch_bounds__(256) void transpose_kernel(const float* __restrict__ x) {
    int idx = blockIdx.x * 256 + threadIdx.x;
    if (blockIdx.x < 16) { g_ps[idx] = 0.f; g_ps2[idx] = 0.f; }
    int b = idx & 15, w = (idx >> 4) & 31, h = (idx >> 9) & 31, c = idx >> 14;
    g_xT[idx] = x[(((b << 6) + c) << 10) + (h << 5) + w];
}

// ---------------------------------------------------------------------------
// One CTA (128 thr, 4 warps) per output location.
// D[64 x 16] = W_loc[64 x 576] * X_loc[576 x 16], mma.sync tf32 (both operands
// single tf32-RNA; rel err ~3e-4 < 1e-3).
//
// W pipeline, 256B-burst edition: warp-private 2-slot ring; stage s (s=0..8)
// holds 16 rows x 256B, where row r's bytes are the CONTIGUOUS gmem range
// [r_row_base + s*256, +256) (4 kb-blocks). Fill: 8 warp-instructions per
// stage, each covering 2 rows x 256B contiguous (lane L: row=L>>4, off=
// (L&15)*16B) -> DRAM sees 256B sequential bursts instead of scattered 64B.
// Slot layout: byte (row<<8) + (((kbl ^ row)&3)<<6) + tg*16  [XOR swizzle ->
// LDS.128 conflict-free per 8-lane phase: g parity splits banks 0-15/16-31].
// B slot (kpair kp, col n): 8B at 8*(kp*18 + n) (conflict-free, as R11).
// ---------------------------------------------------------------------------
__global__ __launch_bounds__(128, 3) void conv_mma_kernel(const float* __restrict__ wgt,
                                                          const float* __restrict__ bias,
                                                          float* __restrict__ out) {
    extern __shared__ uint32_t bsm[];                // B fragments
    char* wsm = (char*)bsm + SMEM_B_BYTES;           // W pipeline
    const int tid = threadIdx.x, wid = tid >> 5, lane = tid & 31;
    const int tg = lane & 3, g = lane >> 2;
    const int loc = blockIdx.x, li = loc >> 5, lj = loc & 31;

    // Fill-side per-thread geometry: rows {2i + rhalf}, contiguous 16B at koff.
    const int rhalf = lane >> 4;                     // 0/1
    const int koff = lane & 15;                      // 16B chunk within 256B
    const int kbl_f = (lane >> 2) & 3;               // kb-local of this chunk
    const float* src0 = wgt + ((size_t)((wid << 4) + rhalf) * LOCS + loc) * KVOL
                      + (koff << 2);
    char* dst0 = wsm + (wid << 13) + (rhalf << 8) + ((lane & 3) << 4);

#define FILL_STAGE(s, ss)                                                         \
    _Pragma("unroll")                                                             \
    for (int i = 0; i < 8; i++) {                                                 \
        int swz = ((kbl_f ^ (((i & 1) << 1) + rhalf)) & 3) << 6;                  \
        cp16(dst0 + ((ss) << 12) + (i << 9) + swz,                                \
             src0 + (size_t)i * (2 * LOCS * KVOL) + (s) * 64);                    \
    }

    // Prologue: stages 0 and 1 in flight.
    FILL_STAGE(0, 0); CP_COMMIT();
    FILL_STAGE(1, 1); CP_COMMIT();

    // ---- Stage B = X tf32 fragments ----
    for (int t = tid; t < 288 * 4; t += 128) {
        int kp = t >> 2, nq = t & 3;                 // kpair, n-quad
        float4 xq[2];
#pragma unroll
        for (int h = 0; h < 2; h++) {
            int k = 2 * kp + h;
            int c = k / 9, r = k - c * 9, p = r / 3, q = r - p * 3;
            int ih = li + p - 1, iw = lj + q - 1;
            xq[h] = make_float4(0.f, 0.f, 0.f, 0.f);
            if ((unsigned)ih < 32u && (unsigned)iw < 32u)
                xq[h] = *(const float4*)&g_xT[(((((c << 5) + ih) << 5) + iw) << 4) + (nq << 2)];
        }
        const float* x0 = &xq[0].x;
        const float* x1 = &xq[1].x;
#pragma unroll
        for (int e = 0; e < 4; e++) {
            int n = (nq << 2) + e;
            uint32_t idx = (uint32_t)(kp * BSLOT_STRIDE + n) << 1;
            bsm[idx] = tf32_rna(x0[e]);
            bsm[idx + 1] = tf32_rna(x1[e]);
        }
    }
    __syncthreads();

    // ---- Main loop: 9 stages x 4 kb ----
    float d[2][4] = {{0.f, 0.f, 0.f, 0.f}, {0.f, 0.f, 0.f, 0.f}};
    const char* acons = wsm + (wid << 13) + (tg << 4);

    for (int st = 0; st < NSTAGES; st++) {
        CP_WAIT1();
        __syncwarp();
        const int ss = st & 1;
        const char* ap = acons + (ss << 12);
#pragma unroll
        for (int kbl = 0; kbl < 4; kbl++) {
            int sw = ((kbl ^ g) & 3) << 6;           // (g+8)&3 == g&3 -> same sw
            float4 A0 = *(const float4*)(ap + (g << 8) + sw);
            float4 A1 = *(const float4*)(ap + ((g + 8) << 8) + sw);
            int kb = (st << 2) + kbl;
#pragma unroll
            for (int s = 0; s < 2; s++) {
                uint32_t aa[4];
                aa[0] = tf32_rna(s ? A0.z : A0.x);
                aa[1] = tf32_rna(s ? A1.z : A1.x);
                aa[2] = tf32_rna(s ? A0.w : A0.y);
                aa[3] = tf32_rna(s ? A1.w : A1.y);
                int kp = (kb << 3) + (tg << 1) + s;
#pragma unroll
                for (int nt = 0; nt < 2; nt++) {
                    int n = g + (nt << 3);
                    uint2 q = *(const uint2*)&bsm[(uint32_t)(kp * BSLOT_STRIDE + n) << 1];
                    mma_tf32(d[nt], aa, q.x, q.y);
                }
            }
        }
        __syncwarp();                                 // slot fully read by warp
        if (st + 2 < NSTAGES) { FILL_STAGE(st + 2, ss); }
        CP_COMMIT();                                  // one group per stage
    }

    // ---- Epilogue: lane (g,tg) holds rows o0=16w+g, o1=o0+8;
    //      cols b = {2tg, 2tg+1} per n-tile. ----
    int o0 = (wid << 4) + g, o1 = o0 + 8;
    float bv0 = bias[(o0 << 10) + loc];
    float bv1 = bias[(o1 << 10) + loc];
    float s0 = 0.f, q0 = 0.f, s1 = 0.f, q1 = 0.f;
#pragma unroll
    for (int nt = 0; nt < 2; nt++) {
#pragma unroll
        for (int e = 0; e < 2; e++) {
            int b = (nt << 3) + (tg << 1) + e;
            float v0 = d[nt][e] + bv0;
            float v1 = d[nt][e + 2] + bv1;
            out[(((b << 6) + o0) << 10) + loc] = v0;
            out[(((b << 6) + o1) << 10) + loc] = v1;
            s0 += v0; q0 = fmaf(v0, v0, q0);
            s1 += v1; q1 = fmaf(v1, v1, q1);
        }
    }
#pragma unroll
    for (int m = 1; m < 4; m <<= 1) {
        s0 += __shfl_down_sync(0xffffffffu, s0, m, 4);
        q0 += __shfl_down_sync(0xffffffffu, q0, m, 4);
        s1 += __shfl_down_sync(0xffffffffu, s1, m, 4);
        q1 += __shfl_down_sync(0xffffffffu, q1, m, 4);
    }
    if (tg == 0) {
        int bkt = loc & 63;
        atomicAdd(&g_ps[(bkt << 6) + o0], s0);
        atomicAdd(&g_ps2[(bkt << 6) + o0], q0);
        atomicAdd(&g_ps[(bkt << 6) + o1], s1);
        atomicAdd(&g_ps2[(bkt << 6) + o1], q1);
    }
}

// ---------------------------------------------------------------------------
__global__ void params_kernel(const float* __restrict__ gamma,
                              const float* __restrict__ beta) {
    int o = threadIdx.x;
    float S = 0.f, S2 = 0.f;
    for (int k = 0; k < 64; k++) { S += g_ps[(k << 6) + o]; S2 += g_ps2[(k << 6) + o]; }
    const float inv = 1.f / (float)(NB * LOCS);
    float mean = S * inv;
    float var = S2 * inv - mean * mean;              // biased variance (ddof=0)
    float sc = gamma[o] * rsqrtf(var + 1e-5f);
    g_scale[o] = sc;
    g_shift[o] = beta[o] - mean * sc;
}

__global__ __launch_bounds__(256) void finalize_kernel(float* __restrict__ y) {
    int idx = blockIdx.x * 256 + threadIdx.x;
    int o = (idx >> 8) & 63;
    float sc = g_scale[o], sh = g_shift[o];
    float4 v = ((float4*)y)[idx];
    v.x = fmaxf(fmaf(v.x, sc, sh), 0.f);
    v.y = fmaxf(fmaf(v.y, sc, sh), 0.f);
    v.z = fmaxf(fmaf(v.z, sc, sh), 0.f);
    v.w = fmaxf(fmaf(v.w, sc, sh), 0.f);
    ((float4*)y)[idx] = v;
}

extern "C" void kernel_launch(void* const* d_in, const int* in_sizes, int n_in,
                              void* d_out, int out_size) {
    const float* x     = (const float*)d_in[0];
    const float* w     = (const float*)d_in[1];
    const float* bias  = (const float*)d_in[2];
    const float* gamma = (const float*)d_in[3];
    const float* beta  = (const float*)d_in[4];
    float* out = (float*)d_out;

    cudaFuncSetAttribute(conv_mma_kernel, cudaFuncAttributeMaxDynamicSharedMemorySize,
                         SMEM_TOTAL);

    transpose_kernel<<<4096, 256>>>(x);                  // + zero BN partials
    conv_mma_kernel<<<1024, 128, SMEM_TOTAL>>>(w, bias, out);
    params_kernel<<<1, 64>>>(gamma, beta);
    finalize_kernel<<<1024, 256>>>(out);
}